// round 4
// baseline (speedup 1.0000x reference)
#include <cuda_runtime.h>

#define DMODEL 1024
#define NHEADS 16
#define DK     64
#define BATCH  2
#define SEQ    2048
#define MTOT   (BATCH * SEQ)   // 4096

// Scratch (static __device__ — allocation-free per harness rules)
__device__ float g_Q[(size_t)BATCH * NHEADS * SEQ * DK];
__device__ float g_K[(size_t)BATCH * NHEADS * SEQ * DK];
__device__ float g_V[(size_t)BATCH * NHEADS * SEQ * DK];
__device__ float g_ctx[(size_t)BATCH * SEQ * DMODEL];

// ---------------------------------------------------------------------------
// Fused QKV projection GEMM.
// C[m,n] = sum_k x[m,k] * W[n,k] + bias[n]   (NT gemm, both K-contiguous)
// BM=BN=128, BK=8, 256 threads, 8x8 per-thread register tile.
// Logical N = 3072 (Q|K|V); each 128-wide block lies inside one weight matrix.
// Output scattered into [b, h, s, dk] layout.
// ---------------------------------------------------------------------------
__global__ __launch_bounds__(256, 2)
void qkv_gemm_kernel(const float* __restrict__ x,
                     const float* __restrict__ Wq, const float* __restrict__ bq,
                     const float* __restrict__ Wk, const float* __restrict__ bk,
                     const float* __restrict__ Wv, const float* __restrict__ bv)
{
    __shared__ float As[8][132];
    __shared__ float Bs[8][132];

    const int m0  = blockIdx.x * 128;
    const int n0g = blockIdx.y * 128;          // 0..3071
    const int wsel = n0g >> 10;                // which of Q/K/V
    const int n0   = n0g & 1023;               // column inside that matrix

    const float* __restrict__ W   = (wsel == 0) ? Wq : ((wsel == 1) ? Wk : Wv);
    const float* __restrict__ bia = (wsel == 0) ? bq : ((wsel == 1) ? bk : bv);
    float* __restrict__ dst       = (wsel == 0) ? g_Q : ((wsel == 1) ? g_K : g_V);

    const int tid  = threadIdx.x;
    const int tx   = tid & 15;
    const int ty   = tid >> 4;
    const int lrow = tid >> 1;                 // 0..127
    const int lseg = (tid & 1) << 2;           // 0 or 4

    float acc[8][8];
#pragma unroll
    for (int i = 0; i < 8; i++)
#pragma unroll
        for (int j = 0; j < 8; j++) acc[i][j] = 0.f;

    const float* aptr = x + (size_t)(m0 + lrow) * DMODEL + lseg;
    const float* bptr = W + (size_t)(n0 + lrow) * DMODEL + lseg;

    float4 av = *(const float4*)aptr;
    float4 wv = *(const float4*)bptr;

    for (int k0 = 0; k0 < DMODEL; k0 += 8) {
        As[lseg + 0][lrow] = av.x; As[lseg + 1][lrow] = av.y;
        As[lseg + 2][lrow] = av.z; As[lseg + 3][lrow] = av.w;
        Bs[lseg + 0][lrow] = wv.x; Bs[lseg + 1][lrow] = wv.y;
        Bs[lseg + 2][lrow] = wv.z; Bs[lseg + 3][lrow] = wv.w;
        __syncthreads();

        if (k0 + 8 < DMODEL) {                 // prefetch next slab
            av = *(const float4*)(aptr + k0 + 8);
            wv = *(const float4*)(bptr + k0 + 8);
        }

#pragma unroll
        for (int k = 0; k < 8; k++) {
            float4 a0 = *(const float4*)&As[k][ty * 8];
            float4 a1 = *(const float4*)&As[k][ty * 8 + 4];
            float4 b0 = *(const float4*)&Bs[k][tx * 8];
            float4 b1 = *(const float4*)&Bs[k][tx * 8 + 4];
            float a[8] = {a0.x, a0.y, a0.z, a0.w, a1.x, a1.y, a1.z, a1.w};
            float b[8] = {b0.x, b0.y, b0.z, b0.w, b1.x, b1.y, b1.z, b1.w};
#pragma unroll
            for (int i = 0; i < 8; i++)
#pragma unroll
                for (int j = 0; j < 8; j++)
                    acc[i][j] += a[i] * b[j];
        }
        __syncthreads();
    }

#pragma unroll
    for (int i = 0; i < 8; i++) {
        const int m    = m0 + ty * 8 + i;
        const int bb   = m >> 11;              // / SEQ
        const int srow = m & (SEQ - 1);
#pragma unroll
        for (int j = 0; j < 8; j++) {
            const int nl   = n0 + tx * 8 + j;
            const int head = nl >> 6;
            const int dk   = nl & 63;
            dst[((size_t)((bb * NHEADS + head) * SEQ + srow)) * DK + dk] =
                acc[i][j] + bia[nl];
        }
    }
}

// ---------------------------------------------------------------------------
// Output projection GEMM: out[m,n] = sum_k ctx[m,k]*Wo[n,k] + bo[n]
// ---------------------------------------------------------------------------
__global__ __launch_bounds__(256, 2)
void oproj_gemm_kernel(const float* __restrict__ Wo,
                       const float* __restrict__ bo,
                       float* __restrict__ out)
{
    __shared__ float As[8][132];
    __shared__ float Bs[8][132];

    const int m0 = blockIdx.x * 128;
    const int n0 = blockIdx.y * 128;

    const int tid  = threadIdx.x;
    const int tx   = tid & 15;
    const int ty   = tid >> 4;
    const int lrow = tid >> 1;
    const int lseg = (tid & 1) << 2;

    float acc[8][8];
#pragma unroll
    for (int i = 0; i < 8; i++)
#pragma unroll
        for (int j = 0; j < 8; j++) acc[i][j] = 0.f;

    const float* aptr = g_ctx + (size_t)(m0 + lrow) * DMODEL + lseg;
    const float* bptr = Wo    + (size_t)(n0 + lrow) * DMODEL + lseg;

    float4 av = *(const float4*)aptr;
    float4 wv = *(const float4*)bptr;

    for (int k0 = 0; k0 < DMODEL; k0 += 8) {
        As[lseg + 0][lrow] = av.x; As[lseg + 1][lrow] = av.y;
        As[lseg + 2][lrow] = av.z; As[lseg + 3][lrow] = av.w;
        Bs[lseg + 0][lrow] = wv.x; Bs[lseg + 1][lrow] = wv.y;
        Bs[lseg + 2][lrow] = wv.z; Bs[lseg + 3][lrow] = wv.w;
        __syncthreads();

        if (k0 + 8 < DMODEL) {
            av = *(const float4*)(aptr + k0 + 8);
            wv = *(const float4*)(bptr + k0 + 8);
        }

#pragma unroll
        for (int k = 0; k < 8; k++) {
            float4 a0 = *(const float4*)&As[k][ty * 8];
            float4 a1 = *(const float4*)&As[k][ty * 8 + 4];
            float4 b0 = *(const float4*)&Bs[k][tx * 8];
            float4 b1 = *(const float4*)&Bs[k][tx * 8 + 4];
            float a[8] = {a0.x, a0.y, a0.z, a0.w, a1.x, a1.y, a1.z, a1.w};
            float b[8] = {b0.x, b0.y, b0.z, b0.w, b1.x, b1.y, b1.z, b1.w};
#pragma unroll
            for (int i = 0; i < 8; i++)
#pragma unroll
                for (int j = 0; j < 8; j++)
                    acc[i][j] += a[i] * b[j];
        }
        __syncthreads();
    }

#pragma unroll
    for (int i = 0; i < 8; i++) {
        const int m = m0 + ty * 8 + i;
#pragma unroll
        for (int j = 0; j < 8; j++) {
            const int n = n0 + tx * 8 + j;
            out[(size_t)m * DMODEL + n] = acc[i][j] + bo[n];
        }
    }
}

// ---------------------------------------------------------------------------
// Causal flash attention, fp32.
// One block per (b, h, 64-query tile). 256 threads as 16x16; each thread owns
// a 4x4 micro-tile of the 64x64 score tile and of the 64-wide output.
// Online softmax; key blocks beyond the causal frontier are skipped.
// ---------------------------------------------------------------------------
#define ASTR 65   // smem row stride (pad vs 64 -> <=2-way bank conflicts)

__global__ __launch_bounds__(256)
void attn_kernel()
{
    extern __shared__ float sm[];
    float* Qs = sm;                  // 64 x ASTR
    float* Ks = Qs + 64 * ASTR;
    float* Vs = Ks + 64 * ASTR;
    float* Ps = Vs + 64 * ASTR;

    const int bid = blockIdx.x;
    const int qb  = bid & 31;                  // query tile (S/64 = 32)
    const int h   = (bid >> 5) & (NHEADS - 1);
    const int b   = bid >> 9;

    const int tid = threadIdx.x;
    const int tx  = tid & 15;
    const int ty  = tid >> 4;

    const size_t headbase = (size_t)(b * NHEADS + h) * SEQ * DK;
    const float* Qbase = g_Q + headbase + (size_t)qb * 64 * DK;
    const float* Kh    = g_K + headbase;
    const float* Vh    = g_V + headbase;

    for (int idx = tid; idx < 64 * 64; idx += 256) {
        const int r = idx >> 6, d = idx & 63;
        Qs[r * ASTR + d] = Qbase[r * DK + d];
    }

    float o[4][4];
    float mrow[4], lrow[4];
#pragma unroll
    for (int i = 0; i < 4; i++) {
        mrow[i] = -1e30f;
        lrow[i] = 0.f;
#pragma unroll
        for (int j = 0; j < 4; j++) o[i][j] = 0.f;
    }

    for (int jt = 0; jt <= qb; jt++) {
        __syncthreads();   // Qs visible (iter 0); prior PV reads done (iter>0)

        const float* Kb = Kh + (size_t)jt * 64 * DK;
        const float* Vb = Vh + (size_t)jt * 64 * DK;
        for (int idx = tid; idx < 64 * 64; idx += 256) {
            const int r = idx >> 6, d = idx & 63;
            Ks[r * ASTR + d] = Kb[r * DK + d];
            Vs[r * ASTR + d] = Vb[r * DK + d];
        }
        __syncthreads();

        // S = Q K^T for this tile
        float s[4][4];
#pragma unroll
        for (int i = 0; i < 4; i++)
#pragma unroll
            for (int j = 0; j < 4; j++) s[i][j] = 0.f;

#pragma unroll 16
        for (int d = 0; d < 64; d++) {
            float qv[4], kv[4];
#pragma unroll
            for (int i = 0; i < 4; i++) qv[i] = Qs[(ty * 4 + i) * ASTR + d];
#pragma unroll
            for (int j = 0; j < 4; j++) kv[j] = Ks[(tx * 4 + j) * ASTR + d];
#pragma unroll
            for (int i = 0; i < 4; i++)
#pragma unroll
                for (int j = 0; j < 4; j++)
                    s[i][j] += qv[i] * kv[j];
        }

        const float scale = 0.125f;            // 1/sqrt(DK)
        if (jt == qb) {                        // diagonal tile: causal mask
#pragma unroll
            for (int i = 0; i < 4; i++) {
                const int qg = (qb << 6) + (ty << 2) + i;
#pragma unroll
                for (int j = 0; j < 4; j++) {
                    const int kg = (jt << 6) + (tx << 2) + j;
                    s[i][j] = (kg <= qg) ? s[i][j] * scale : -1e30f;
                }
            }
        } else {
#pragma unroll
            for (int i = 0; i < 4; i++)
#pragma unroll
                for (int j = 0; j < 4; j++) s[i][j] *= scale;
        }

        // online softmax: row max + rescale (16-lane xor reductions)
        float mnew[4], alpha[4];
#pragma unroll
        for (int i = 0; i < 4; i++) {
            float v = fmaxf(fmaxf(s[i][0], s[i][1]), fmaxf(s[i][2], s[i][3]));
#pragma unroll
            for (int off = 8; off > 0; off >>= 1)
                v = fmaxf(v, __shfl_xor_sync(0xffffffffu, v, off));
            mnew[i]  = fmaxf(mrow[i], v);
            alpha[i] = __expf(mrow[i] - mnew[i]);
        }
#pragma unroll
        for (int i = 0; i < 4; i++) {
            float rs = 0.f;
#pragma unroll
            for (int j = 0; j < 4; j++) {
                const float p = __expf(s[i][j] - mnew[i]);
                s[i][j] = p;
                rs += p;
            }
#pragma unroll
            for (int off = 8; off > 0; off >>= 1)
                rs += __shfl_xor_sync(0xffffffffu, rs, off);
            lrow[i] = lrow[i] * alpha[i] + rs;
            mrow[i] = mnew[i];
#pragma unroll
            for (int j = 0; j < 4; j++) o[i][j] *= alpha[i];
        }

        // publish P tile, then O += P V
#pragma unroll
        for (int i = 0; i < 4; i++)
#pragma unroll
            for (int j = 0; j < 4; j++)
                Ps[(ty * 4 + i) * ASTR + tx * 4 + j] = s[i][j];
        __syncthreads();

#pragma unroll 16
        for (int kk = 0; kk < 64; kk++) {
            float pv[4], vv[4];
#pragma unroll
            for (int i = 0; i < 4; i++) pv[i] = Ps[(ty * 4 + i) * ASTR + kk];
#pragma unroll
            for (int j = 0; j < 4; j++) vv[j] = Vs[kk * ASTR + tx * 4 + j];
#pragma unroll
            for (int i = 0; i < 4; i++)
#pragma unroll
                for (int j = 0; j < 4; j++)
                    o[i][j] += pv[i] * vv[j];
        }
    }

    // normalize and write context in [b, s, h*64+dk] layout
#pragma unroll
    for (int i = 0; i < 4; i++) {
        const int r = (qb << 6) + (ty << 2) + i;
        const float inv = 1.f / lrow[i];
#pragma unroll
        for (int j = 0; j < 4; j++) {
            g_ctx[((size_t)(b * SEQ + r)) * DMODEL + h * DK + tx * 4 + j] =
                o[i][j] * inv;
        }
    }
}

// ---------------------------------------------------------------------------
extern "C" void kernel_launch(void* const* d_in, const int* in_sizes, int n_in,
                              void* d_out, int out_size)
{
    const float* x  = (const float*)d_in[0];
    // d_in[1] = mask (causal; statically known, unused)
    const float* Wq = (const float*)d_in[2];
    const float* bq = (const float*)d_in[3];
    const float* Wk = (const float*)d_in[4];
    const float* bk = (const float*)d_in[5];
    const float* Wv = (const float*)d_in[6];
    const float* bv = (const float*)d_in[7];
    const float* Wo = (const float*)d_in[8];
    const float* bo = (const float*)d_in[9];
    float* out = (float*)d_out;

    const int attn_smem = 4 * 64 * ASTR * (int)sizeof(float);   // 66560 B
    cudaFuncSetAttribute(attn_kernel,
                         cudaFuncAttributeMaxDynamicSharedMemorySize, attn_smem);

    dim3 blk(256);
    qkv_gemm_kernel<<<dim3(MTOT / 128, 3 * DMODEL / 128), blk>>>(
        x, Wq, bq, Wk, bk, Wv, bv);
    attn_kernel<<<BATCH * NHEADS * (SEQ / 64), blk, attn_smem>>>();
    oproj_gemm_kernel<<<dim3(MTOT / 128, DMODEL / 128), blk>>>(Wo, bo, out);
}